// round 11
// baseline (speedup 1.0000x reference)
#include <cuda_runtime.h>

#define N_NODES 100000
#define N_EDGES 1600000
#define HID 64
#define DENSE 128
#define OUTD 10
#define N_GRAPHS 128
#define SCAN_NB 98
#define INVN (1.f / (float)N_NODES)
#define INVG (1.f / (float)N_GRAPHS)

typedef unsigned long long u64t;

// ---------------- packed f32x2 helpers (R3-proven) ------------------------
__device__ __forceinline__ u64t pk2(float lo, float hi) {
    u64t r; asm("mov.b64 %0,{%1,%2};" : "=l"(r) : "f"(lo), "f"(hi)); return r;
}
__device__ __forceinline__ void fma2(u64t& d, u64t a, u64t b) {
    asm("fma.rn.f32x2 %0,%1,%2,%0;" : "+l"(d) : "l"(a), "l"(b));
}
__device__ __forceinline__ float2 up2(u64t v) {
    float2 r; asm("mov.b64 {%0,%1},%2;" : "=f"(r.x), "=f"(r.y) : "l"(v)); return r;
}

// ---------------- device scratch ------------------------------------------
__device__ __align__(16) float g_Xa[N_NODES * HID];
__device__ __align__(16) float g_Y1[N_NODES * DENSE];
__device__ int   g_deg[N_NODES];
__device__ int   g_rowptr[N_NODES];
__device__ int   g_cursor[N_NODES];
__device__ int   g_col[N_EDGES];
__device__ int   g_bsum[128];
__device__ __align__(16) float g_stats128[4 * 2 * DENSE];
__device__ __align__(16) float g_stats64 [4 * 2 * HID];
__device__ __align__(16) float g_statsF[4 * DENSE];
__device__ __align__(16) float g_reps[N_GRAPHS * HID];
__device__ __align__(16) float g_T1[N_GRAPHS * DENSE];
__device__ __align__(16) float g_T2[N_GRAPHS * DENSE];

// ---------------- setup ---------------------------------------------------
__global__ void k_setup() {
    int t = blockIdx.x * blockDim.x + threadIdx.x;
    if (t < N_NODES)          g_deg[t] = 0;
    if (t < 4 * 2 * DENSE)    g_stats128[t] = 0.f;
    if (t < 4 * 2 * HID)      g_stats64[t]  = 0.f;
    if (t < 4 * DENSE)        g_statsF[t] = 0.f;
}

// ---------------- CSR build -----------------------------------------------
__global__ void k_hist(const int* __restrict__ ei) {
    int e = blockIdx.x * blockDim.x + threadIdx.x;
    if (e < N_EDGES) atomicAdd(&g_deg[ei[N_EDGES + e]], 1);
}

__global__ void k_scan1() {
    __shared__ int ss[256];
    int tid = threadIdx.x;
    int base = blockIdx.x * 1024 + tid * 4;
    int s = 0;
#pragma unroll
    for (int i = 0; i < 4; i++) { int idx = base + i; if (idx < N_NODES) s += g_deg[idx]; }
    ss[tid] = s; __syncthreads();
    for (int off = 128; off > 0; off >>= 1) {
        if (tid < off) ss[tid] += ss[tid + off];
        __syncthreads();
    }
    if (tid == 0) g_bsum[blockIdx.x] = ss[0];   // raw block sums
}

// scan3 computes its own global offset (scan2 eliminated — R8-validated)
__global__ void k_scan3() {
    __shared__ int sc[256];
    __shared__ int sb2[128];
    __shared__ int sOff;
    int tid = threadIdx.x;
    if (tid < SCAN_NB) sb2[tid] = g_bsum[tid];
    __syncthreads();
    if (tid == 0) {
        int off = 0;
        for (int i = 0; i < (int)blockIdx.x; i++) off += sb2[i];
        sOff = off;
    }
    int base = blockIdx.x * 1024 + tid * 4;
    int d[4]; int s = 0;
#pragma unroll
    for (int i = 0; i < 4; i++) {
        d[i] = (base + i < N_NODES) ? g_deg[base + i] : 0;
        s += d[i];
    }
    sc[tid] = s; __syncthreads();
    for (int off = 1; off < 256; off <<= 1) {
        int v = (tid >= off) ? sc[tid - off] : 0;
        __syncthreads();
        sc[tid] += v;
        __syncthreads();
    }
    int off = sOff + sc[tid] - s;
#pragma unroll
    for (int i = 0; i < 4; i++) {
        if (base + i < N_NODES) { g_rowptr[base + i] = off; g_cursor[base + i] = off; off += d[i]; }
    }
}

__global__ void k_fill(const int* __restrict__ ei) {
    int e = blockIdx.x * blockDim.x + threadIdx.x;
    if (e < N_EDGES) {
        int d = ei[N_EDGES + e];
        int p = atomicAdd(&g_cursor[d], 1);
        g_col[p] = ei[e];
    }
}

// ============ FUSED aggregation + GEMM1 ===================================
// 256 threads, occ 2 (R10-gemm1 shape). Phase 1: half-warp-per-row gather
// builds the GIN-aggregated A tile directly in smem (no g_H). Phase 2:
// R10-exact FFMA2 mainloop Y1 = A @ W1 with fused column stats.
#define G1_SMEM_FLOATS (128*64 + 64*128 + 2*128 + 2*HID)
__global__ void __launch_bounds__(256, 2) k_ag1(
        const int* __restrict__ x_idx, const float* __restrict__ emb,
        const float* __restrict__ X, const float* __restrict__ epsArr,
        const float* __restrict__ W, float* __restrict__ Y,
        const float* __restrict__ statsIn, const float* __restrict__ gam,
        const float* __restrict__ bet, float* __restrict__ statsOut, int layer) {
    extern __shared__ float sm[];
    float* sA = sm;                 // [128][64]
    float* sW = sm + 128 * 64;      // [64][128] k-major
    float* sS = sW + 64 * 128;      // [256]
    float* sa = sS + 256;           // [64]
    float* sb = sa + HID;           // [64]
    int t = threadIdx.x;
    int row0 = blockIdx.x * 128;

    {   // W tile
        const float4* W4 = (const float4*)W;
        float4* sW4 = (float4*)sW;
#pragma unroll
        for (int i = 0; i < 8; i++) sW4[t + i * 256] = W4[t + i * 256];
    }
    if (layer > 0 && t < HID) {
        float s = statsIn[t], q = statsIn[HID + t];
        float m = s * INVN;
        float var = q * INVN - m * m;
        float a = gam[t] * rsqrtf(var + 1e-5f);
        sa[t] = a;
        sb[t] = fmaf(-m, a, bet[t]);
    }
    sS[t] = 0.f;
    __syncthreads();

    // ---- phase 1: gather A tile (half-warp per row, float4 per lane) ----
    {
        int hw = t >> 4, l = t & 15;
        float ev = 1.f + epsArr[layer];
        float4 ta, tb;
        if (layer > 0) { ta = ((const float4*)sa)[l]; tb = ((const float4*)sb)[l]; }
#pragma unroll 1
        for (int rr = 0; rr < 8; rr++) {
            int row = hw * 8 + rr;
            int gr = row0 + row;
            float4 acc = make_float4(0.f, 0.f, 0.f, 0.f);
            if (gr < N_NODES) {
                int start = g_rowptr[gr], deg = g_deg[gr];
                if (layer == 0) {
                    int si = __ldg(&x_idx[gr]);
                    float4 v = ((const float4*)emb)[si * 16 + l];
                    acc.x = ev * v.x; acc.y = ev * v.y;
                    acc.z = ev * v.z; acc.w = ev * v.w;
                    int j = 0;
                    for (; j + 1 < deg; j += 2) {
                        int n0 = __ldg(&x_idx[g_col[start + j]]);
                        int n1 = __ldg(&x_idx[g_col[start + j + 1]]);
                        float4 p = ((const float4*)emb)[n0 * 16 + l];
                        float4 q = ((const float4*)emb)[n1 * 16 + l];
                        acc.x += p.x + q.x; acc.y += p.y + q.y;
                        acc.z += p.z + q.z; acc.w += p.w + q.w;
                    }
                    if (j < deg) {
                        int n0 = __ldg(&x_idx[g_col[start + j]]);
                        float4 p = ((const float4*)emb)[n0 * 16 + l];
                        acc.x += p.x; acc.y += p.y; acc.z += p.z; acc.w += p.w;
                    }
                } else {
                    float4 v = ((const float4*)X)[(size_t)gr * 16 + l];
                    acc.x = ev * fmaxf(fmaf(ta.x, v.x, tb.x), 0.f);
                    acc.y = ev * fmaxf(fmaf(ta.y, v.y, tb.y), 0.f);
                    acc.z = ev * fmaxf(fmaf(ta.z, v.z, tb.z), 0.f);
                    acc.w = ev * fmaxf(fmaf(ta.w, v.w, tb.w), 0.f);
                    int j = 0;
                    for (; j + 1 < deg; j += 2) {
                        int n0 = g_col[start + j], n1 = g_col[start + j + 1];
                        float4 p = ((const float4*)X)[(size_t)n0 * 16 + l];
                        float4 q = ((const float4*)X)[(size_t)n1 * 16 + l];
                        acc.x += fmaxf(fmaf(ta.x, p.x, tb.x), 0.f)
                               + fmaxf(fmaf(ta.x, q.x, tb.x), 0.f);
                        acc.y += fmaxf(fmaf(ta.y, p.y, tb.y), 0.f)
                               + fmaxf(fmaf(ta.y, q.y, tb.y), 0.f);
                        acc.z += fmaxf(fmaf(ta.z, p.z, tb.z), 0.f)
                               + fmaxf(fmaf(ta.z, q.z, tb.z), 0.f);
                        acc.w += fmaxf(fmaf(ta.w, p.w, tb.w), 0.f)
                               + fmaxf(fmaf(ta.w, q.w, tb.w), 0.f);
                    }
                    if (j < deg) {
                        int n0 = g_col[start + j];
                        float4 p = ((const float4*)X)[(size_t)n0 * 16 + l];
                        acc.x += fmaxf(fmaf(ta.x, p.x, tb.x), 0.f);
                        acc.y += fmaxf(fmaf(ta.y, p.y, tb.y), 0.f);
                        acc.z += fmaxf(fmaf(ta.z, p.z, tb.z), 0.f);
                        acc.w += fmaxf(fmaf(ta.w, p.w, tb.w), 0.f);
                    }
                }
            }
            *(float4*)(sA + row * 64 + l * 4) = acc;
        }
    }
    __syncthreads();

    // ---- phase 2: R10-exact FFMA2 mainloop ----
    int tx = t & 15, ty = t >> 4;
    const float* aBase = sA + ty * 8 * 64;
    const float4* w4 = (const float4*)sW;

    u64t acc[8][4];
#pragma unroll
    for (int i = 0; i < 8; i++)
#pragma unroll
        for (int j = 0; j < 4; j++) acc[i][j] = pk2(0.f, 0.f);

#pragma unroll 8
    for (int k = 0; k < 64; k++) {
        float4 wa = w4[k * 32 + tx];
        float4 wb = w4[k * 32 + 16 + tx];
        u64t w01 = pk2(wa.x, wa.y), w23 = pk2(wa.z, wa.w);
        u64t w45 = pk2(wb.x, wb.y), w67 = pk2(wb.z, wb.w);
#pragma unroll
        for (int i = 0; i < 8; i++) {
            float a = aBase[i * 64 + k];
            u64t a2 = pk2(a, a);
            fma2(acc[i][0], a2, w01);
            fma2(acc[i][1], a2, w23);
            fma2(acc[i][2], a2, w45);
            fma2(acc[i][3], a2, w67);
        }
    }

    float cs[8], cq[8];
#pragma unroll
    for (int j = 0; j < 8; j++) { cs[j] = 0.f; cq[j] = 0.f; }
#pragma unroll
    for (int i = 0; i < 8; i++) {
        float2 p0 = up2(acc[i][0]), p1 = up2(acc[i][1]);
        float2 p2 = up2(acc[i][2]), p3 = up2(acc[i][3]);
        int gr = row0 + ty * 8 + i;
        if (gr < N_NODES) {
            *(float4*)(Y + (size_t)gr * 128 + tx * 4) = make_float4(p0.x, p0.y, p1.x, p1.y);
            *(float4*)(Y + (size_t)gr * 128 + 64 + tx * 4) = make_float4(p2.x, p2.y, p3.x, p3.y);
        }
        cs[0] += p0.x; cq[0] += p0.x * p0.x;
        cs[1] += p0.y; cq[1] += p0.y * p0.y;
        cs[2] += p1.x; cq[2] += p1.x * p1.x;
        cs[3] += p1.y; cq[3] += p1.y * p1.y;
        cs[4] += p2.x; cq[4] += p2.x * p2.x;
        cs[5] += p2.y; cq[5] += p2.y * p2.y;
        cs[6] += p3.x; cq[6] += p3.x * p3.x;
        cs[7] += p3.y; cq[7] += p3.y * p3.y;
    }
#pragma unroll
    for (int j = 0; j < 4; j++) {
        atomicAdd(&sS[tx * 4 + j], cs[j]);
        atomicAdd(&sS[128 + tx * 4 + j], cq[j]);
        atomicAdd(&sS[64 + tx * 4 + j], cs[4 + j]);
        atomicAdd(&sS[128 + 64 + tx * 4 + j], cq[4 + j]);
    }
    __syncthreads();
    atomicAdd(&statsOut[t], sS[t]);
}

// ---------------- GEMM2: row-pair FFMA2 with transposed A tile (R10) ------
#define SAT2 132
#define G2_SMEM_FLOATS (128*SAT2 + 128*64 + 128 + 2*128)
__global__ void __launch_bounds__(256, 2) k_gemm2(const float* __restrict__ Yin,
                                                  const float* __restrict__ W,
                                                  float* __restrict__ Xout,
                                                  const float* __restrict__ statsIn,
                                                  const float* __restrict__ gam,
                                                  const float* __restrict__ bet,
                                                  float* __restrict__ statsOut) {
    extern __shared__ float sm[];
    float* sAT = sm;                      // [128 k][SAT2]
    float* sW  = sm + 128 * SAT2;         // [128][64] k-major
    float* sS  = sW + 128 * 64;           // [128]
    float* sTa = sS + 128;
    float* sTb = sTa + 128;
    int t = threadIdx.x;
    int row0 = blockIdx.x * 128;

    if (t < 128) {
        float s = statsIn[t], q = statsIn[128 + t];
        float m = s * INVN;
        float var = q * INVN - m * m;
        float a = gam[t] * rsqrtf(var + 1e-5f);
        sTa[t] = a;
        sTb[t] = fmaf(-m, a, bet[t]);
        sS[t] = 0.f;
    }
    __syncthreads();

    {   // W tile
        const float4* W4 = (const float4*)W;
        float4* sW4 = (float4*)sW;
#pragma unroll
        for (int i = 0; i < 8; i++) sW4[t + i * 256] = W4[t + i * 256];
    }
    {   // A tile with BN+relu transform, stored TRANSPOSED [k][SAT2]
        int r = t >> 1, kh = (t & 1) * 64;
        int gr = row0 + r;
        if (gr < N_NODES) {
            const float4* src = (const float4*)(Yin + (size_t)gr * 128 + kh);
#pragma unroll
            for (int i = 0; i < 16; i++) {
                float4 y = src[i];
                float4 ta = *(const float4*)(sTa + kh + i * 4);
                float4 tb = *(const float4*)(sTb + kh + i * 4);
                int k0 = kh + i * 4;
                sAT[(k0 + 0) * SAT2 + r] = fmaxf(fmaf(ta.x, y.x, tb.x), 0.f);
                sAT[(k0 + 1) * SAT2 + r] = fmaxf(fmaf(ta.y, y.y, tb.y), 0.f);
                sAT[(k0 + 2) * SAT2 + r] = fmaxf(fmaf(ta.z, y.z, tb.z), 0.f);
                sAT[(k0 + 3) * SAT2 + r] = fmaxf(fmaf(ta.w, y.w, tb.w), 0.f);
            }
        } else {
#pragma unroll
            for (int i = 0; i < 16; i++) {
                int k0 = kh + i * 4;
                sAT[(k0 + 0) * SAT2 + r] = 0.f;
                sAT[(k0 + 1) * SAT2 + r] = 0.f;
                sAT[(k0 + 2) * SAT2 + r] = 0.f;
                sAT[(k0 + 3) * SAT2 + r] = 0.f;
            }
        }
    }
    __syncthreads();

    int tx = t & 15, ty = t >> 4;
    const float* aT = sAT + ty * 8;       // rows ty*8..ty*8+7
    const float4* w4 = (const float4*)sW;

    u64t acc[4][4];                       // [row-pair][col]
#pragma unroll
    for (int i = 0; i < 4; i++)
#pragma unroll
        for (int j = 0; j < 4; j++) acc[i][j] = pk2(0.f, 0.f);

#pragma unroll 8
    for (int k = 0; k < 128; k++) {
        float4 w = w4[k * 16 + tx];
        u64t w0 = pk2(w.x, w.x), w1 = pk2(w.y, w.y);
        u64t w2 = pk2(w.z, w.z), w3 = pk2(w.w, w.w);
        const u64t* ap = (const u64t*)(aT + k * SAT2);
        u64t a0 = ap[0], a1 = ap[1], a2 = ap[2], a3 = ap[3];
        fma2(acc[0][0], a0, w0); fma2(acc[0][1], a0, w1);
        fma2(acc[0][2], a0, w2); fma2(acc[0][3], a0, w3);
        fma2(acc[1][0], a1, w0); fma2(acc[1][1], a1, w1);
        fma2(acc[1][2], a1, w2); fma2(acc[1][3], a1, w3);
        fma2(acc[2][0], a2, w0); fma2(acc[2][1], a2, w1);
        fma2(acc[2][2], a2, w2); fma2(acc[2][3], a2, w3);
        fma2(acc[3][0], a3, w0); fma2(acc[3][1], a3, w1);
        fma2(acc[3][2], a3, w2); fma2(acc[3][3], a3, w3);
    }

    float cs[4] = {0.f, 0.f, 0.f, 0.f}, cq[4] = {0.f, 0.f, 0.f, 0.f};
#pragma unroll
    for (int rp = 0; rp < 4; rp++) {
        float2 p0 = up2(acc[rp][0]), p1 = up2(acc[rp][1]);
        float2 p2 = up2(acc[rp][2]), p3 = up2(acc[rp][3]);
        int gr = row0 + ty * 8 + rp * 2;
        if (gr < N_NODES)
            *(float4*)(Xout + (size_t)gr * 64 + tx * 4) = make_float4(p0.x, p1.x, p2.x, p3.x);
        if (gr + 1 < N_NODES)
            *(float4*)(Xout + (size_t)(gr + 1) * 64 + tx * 4) = make_float4(p0.y, p1.y, p2.y, p3.y);
        cs[0] += p0.x + p0.y; cq[0] += p0.x * p0.x + p0.y * p0.y;
        cs[1] += p1.x + p1.y; cq[1] += p1.x * p1.x + p1.y * p1.y;
        cs[2] += p2.x + p2.y; cq[2] += p2.x * p2.x + p2.y * p2.y;
        cs[3] += p3.x + p3.y; cq[3] += p3.x * p3.x + p3.y * p3.y;
    }
#pragma unroll
    for (int j = 0; j < 4; j++) {
        atomicAdd(&sS[tx * 4 + j], cs[j]);
        atomicAdd(&sS[64 + tx * 4 + j], cq[j]);
    }
    __syncthreads();
    if (t < 128) atomicAdd(&statsOut[t], sS[t]);
}

// ---------------- global mean pool per graph ------------------------------
__global__ void k_pool(const float* __restrict__ X, const int* __restrict__ batch,
                       const float* __restrict__ statsIn,
                       const float* __restrict__ gam, const float* __restrict__ bet) {
    __shared__ float sa[HID], sb[HID];
    __shared__ float sred[4][HID];
    __shared__ int s_lo, s_hi;
    int tid = threadIdx.x, g = blockIdx.x;
    if (tid < HID) {
        float s = statsIn[tid], q = statsIn[HID + tid];
        float m = s * INVN;
        float var = q * INVN - m * m;
        float a = gam[tid] * rsqrtf(var + 1e-5f);
        sa[tid] = a;
        sb[tid] = fmaf(-m, a, bet[tid]);
    }
    if (tid == 0) {
        int lo = 0, hi = N_NODES;
        while (lo < hi) { int mid = (lo + hi) >> 1; if (batch[mid] < g) lo = mid + 1; else hi = mid; }
        s_lo = lo;
        lo = 0; hi = N_NODES; int gg = g + 1;
        while (lo < hi) { int mid = (lo + hi) >> 1; if (batch[mid] < gg) lo = mid + 1; else hi = mid; }
        s_hi = lo;
    }
    __syncthreads();
    int c = tid & 63, rg = tid >> 6;
    float acc = 0.f;
    for (int r = s_lo + rg; r < s_hi; r += 4) {
        float v = fmaf(sa[c], X[(size_t)r * HID + c], sb[c]);
        acc += fmaxf(v, 0.f);
    }
    sred[rg][c] = acc; __syncthreads();
    if (tid < HID) {
        float s = sred[0][c] + sred[1][c] + sred[2][c] + sred[3][c];
        int cnt = s_hi - s_lo;
        g_reps[g * HID + c] = s / (float)(cnt > 0 ? cnt : 1);
    }
}

// ---------------- head GEMMs (in-kernel BN, R8-validated) -----------------
__global__ void kf_gemm(const float* __restrict__ A, const float* __restrict__ W,
                        float* __restrict__ out, float* __restrict__ statsOut,
                        const float* __restrict__ statsIn,
                        const float* __restrict__ gam, const float* __restrict__ bet,
                        int K, int N) {
    __shared__ float ta[DENSE], tb[DENSE];
    int r = blockIdx.x, n = threadIdx.x;
    if (statsIn != 0 && n < K) {
        float s = statsIn[n], q = statsIn[K + n];
        float m = s * INVG;
        float var = q * INVG - m * m;
        float a = gam[n] * rsqrtf(var + 1e-5f);
        ta[n] = a;
        tb[n] = fmaf(-m, a, bet[n]);
    }
    __syncthreads();
    float acc = 0.f;
    for (int k = 0; k < K; k++) {
        float av = A[r * K + k];
        if (statsIn != 0) av = fmaxf(fmaf(ta[k], av, tb[k]), 0.f);
        acc = fmaf(av, W[k * N + n], acc);
    }
    out[r * N + n] = acc;
    atomicAdd(&statsOut[n], acc);
    atomicAdd(&statsOut[N + n], acc * acc);
}

__global__ void kf_out(const float* __restrict__ T2v, const float* __restrict__ Wlin,
                       const float* __restrict__ blin, float* __restrict__ out,
                       const float* __restrict__ statsIn,
                       const float* __restrict__ gam, const float* __restrict__ bet) {
    __shared__ float ta[DENSE], tb[DENSE];
    int r = blockIdx.x, t = threadIdx.x;
    if (t < DENSE) {
        float s = statsIn[t], q = statsIn[DENSE + t];
        float m = s * INVG;
        float var = q * INVG - m * m;
        float a = gam[t] * rsqrtf(var + 1e-5f);
        ta[t] = a;
        tb[t] = fmaf(-m, a, bet[t]);
    }
    __syncthreads();
    if (t < OUTD) {
        float acc = blin[t];
        for (int k = 0; k < DENSE; k++) {
            float av = fmaxf(fmaf(ta[k], T2v[r * DENSE + k], tb[k]), 0.f);
            acc = fmaf(av, Wlin[k * OUTD + t], acc);
        }
        out[r * OUTD + t] = acc;
    }
}

// ---------------- launcher ------------------------------------------------
extern "C" void kernel_launch(void* const* d_in, const int* in_sizes, int n_in,
                              void* d_out, int out_size) {
    (void)in_sizes; (void)n_in; (void)out_size;
    const int*   x_idx = (const int*)d_in[0];
    const int*   ei    = (const int*)d_in[1];
    const int*   batch = (const int*)d_in[2];
    const float* emb   = (const float*)d_in[3];
    const float* eps   = (const float*)d_in[4];
    const float* W1    = (const float*)d_in[5];
    const float* g1    = (const float*)d_in[6];
    const float* b1    = (const float*)d_in[7];
    const float* W2    = (const float*)d_in[8];
    const float* g2    = (const float*)d_in[9];
    const float* b2    = (const float*)d_in[10];
    const float* Wf1   = (const float*)d_in[11];
    const float* gf1   = (const float*)d_in[12];
    const float* bf1   = (const float*)d_in[13];
    const float* Wf2   = (const float*)d_in[14];
    const float* gf2   = (const float*)d_in[15];
    const float* bf2   = (const float*)d_in[16];
    const float* Wlin  = (const float*)d_in[17];
    const float* blin  = (const float*)d_in[18];
    float* out = (float*)d_out;

    float *Xa, *Y1, *s128, *s64, *sF, *reps, *T1, *T2;
    cudaGetSymbolAddress((void**)&Xa,   g_Xa);
    cudaGetSymbolAddress((void**)&Y1,   g_Y1);
    cudaGetSymbolAddress((void**)&s128, g_stats128);
    cudaGetSymbolAddress((void**)&s64,  g_stats64);
    cudaGetSymbolAddress((void**)&sF,   g_statsF);
    cudaGetSymbolAddress((void**)&reps, g_reps);
    cudaGetSymbolAddress((void**)&T1,   g_T1);
    cudaGetSymbolAddress((void**)&T2,   g_T2);

    static const size_t G1_BYTES = G1_SMEM_FLOATS * sizeof(float);
    static const size_t G2_BYTES = G2_SMEM_FLOATS * sizeof(float);
    cudaFuncSetAttribute(k_ag1,   cudaFuncAttributeMaxDynamicSharedMemorySize, (int)G1_BYTES);
    cudaFuncSetAttribute(k_gemm2, cudaFuncAttributeMaxDynamicSharedMemorySize, (int)G2_BYTES);

    k_setup<<<(N_NODES + 255) / 256, 256>>>();
    k_hist <<<(N_EDGES + 255) / 256, 256>>>(ei);
    k_scan1<<<SCAN_NB, 256>>>();
    k_scan3<<<SCAN_NB, 256>>>();
    k_fill <<<(N_EDGES + 255) / 256, 256>>>(ei);

    const int GEMM_GRID = (N_NODES + 127) / 128;   // 782
    for (int l = 0; l < 4; l++) {
        const float* sIn = (l > 0) ? (s64 + (l - 1) * 2 * HID) : s64;
        const float* gIn = (l > 0) ? (g2 + (l - 1) * HID) : g2;
        const float* bIn = (l > 0) ? (b2 + (l - 1) * HID) : b2;
        k_ag1<<<GEMM_GRID, 256, G1_BYTES>>>(x_idx, emb, Xa, eps,
                                            W1 + (size_t)l * HID * DENSE, Y1,
                                            sIn, gIn, bIn,
                                            s128 + l * 2 * DENSE, l);
        k_gemm2<<<GEMM_GRID, 256, G2_BYTES>>>(Y1, W2 + (size_t)l * DENSE * HID, Xa,
                                              s128 + l * 2 * DENSE,
                                              g1 + l * DENSE, b1 + l * DENSE,
                                              s64 + l * 2 * HID);
    }
    k_pool<<<N_GRAPHS, 256>>>(Xa, batch, s64 + 3 * 2 * HID, g2 + 3 * HID, b2 + 3 * HID);

    kf_gemm<<<N_GRAPHS, DENSE>>>(reps, Wf1, T1, sF, (const float*)0,
                                 (const float*)0, (const float*)0, HID, DENSE);
    kf_gemm<<<N_GRAPHS, DENSE>>>(T1, Wf2, T2, sF + 2 * DENSE, sF, gf1, bf1, DENSE, DENSE);
    kf_out<<<N_GRAPHS, DENSE>>>(T2, Wlin, blin, out, sF + 2 * DENSE, gf2, bf2);
}

// round 12
// speedup vs baseline: 1.1043x; 1.1043x over previous
#include <cuda_runtime.h>

#define N_NODES 100000
#define N_EDGES 1600000
#define HID 64
#define DENSE 128
#define OUTD 10
#define N_GRAPHS 128
#define SCAN_NB 98
#define INVN (1.f / (float)N_NODES)
#define INVG (1.f / (float)N_GRAPHS)

typedef unsigned long long u64t;

// ---------------- packed f32x2 helpers (R3-proven) ------------------------
__device__ __forceinline__ u64t pk2(float lo, float hi) {
    u64t r; asm("mov.b64 %0,{%1,%2};" : "=l"(r) : "f"(lo), "f"(hi)); return r;
}
__device__ __forceinline__ void fma2(u64t& d, u64t a, u64t b) {
    asm("fma.rn.f32x2 %0,%1,%2,%0;" : "+l"(d) : "l"(a), "l"(b));
}
__device__ __forceinline__ float2 up2(u64t v) {
    float2 r; asm("mov.b64 {%0,%1},%2;" : "=f"(r.x), "=f"(r.y) : "l"(v)); return r;
}

// ---------------- device scratch ------------------------------------------
__device__ __align__(16) float g_Xa[N_NODES * HID];
__device__ __align__(16) float g_H [N_NODES * HID];
__device__ __align__(16) float g_Y1[N_NODES * DENSE];
__device__ int   g_deg[N_NODES];
__device__ int   g_rowptr[N_NODES];
__device__ int   g_cursor[N_NODES];
__device__ int   g_col[N_EDGES];
__device__ int   g_bsum[128];
__device__ __align__(16) float g_stats128[4 * 2 * DENSE];
__device__ __align__(16) float g_stats64 [4 * 2 * HID];
__device__ __align__(16) float g_statsF[4 * DENSE];
__device__ __align__(16) float g_reps[N_GRAPHS * HID];
__device__ __align__(16) float g_T1[N_GRAPHS * DENSE];
__device__ __align__(16) float g_T2[N_GRAPHS * DENSE];

// ---------------- setup ---------------------------------------------------
__global__ void k_setup() {
    int t = blockIdx.x * blockDim.x + threadIdx.x;
    if (t < N_NODES)          g_deg[t] = 0;
    if (t < 4 * 2 * DENSE)    g_stats128[t] = 0.f;
    if (t < 4 * 2 * HID)      g_stats64[t]  = 0.f;
    if (t < 4 * DENSE)        g_statsF[t] = 0.f;
}

// ---------------- CSR build (2 edges per thread) --------------------------
__global__ void k_hist(const int* __restrict__ ei) {
    int e2 = (blockIdx.x * blockDim.x + threadIdx.x) * 2;
    if (e2 + 1 < N_EDGES) {
        int2 d = *(const int2*)(ei + N_EDGES + e2);
        atomicAdd(&g_deg[d.x], 1);
        atomicAdd(&g_deg[d.y], 1);
    } else if (e2 < N_EDGES) {
        atomicAdd(&g_deg[ei[N_EDGES + e2]], 1);
    }
}

__global__ void k_scan1() {
    __shared__ int ss[256];
    int tid = threadIdx.x;
    int base = blockIdx.x * 1024 + tid * 4;
    int s = 0;
#pragma unroll
    for (int i = 0; i < 4; i++) { int idx = base + i; if (idx < N_NODES) s += g_deg[idx]; }
    ss[tid] = s; __syncthreads();
    for (int off = 128; off > 0; off >>= 1) {
        if (tid < off) ss[tid] += ss[tid + off];
        __syncthreads();
    }
    if (tid == 0) g_bsum[blockIdx.x] = ss[0];   // raw block sums
}

// scan3 computes its own global offset (scan2 eliminated — R8-validated)
__global__ void k_scan3() {
    __shared__ int sc[256];
    __shared__ int sb2[128];
    __shared__ int sOff;
    int tid = threadIdx.x;
    if (tid < SCAN_NB) sb2[tid] = g_bsum[tid];
    __syncthreads();
    if (tid == 0) {
        int off = 0;
        for (int i = 0; i < (int)blockIdx.x; i++) off += sb2[i];
        sOff = off;
    }
    int base = blockIdx.x * 1024 + tid * 4;
    int d[4]; int s = 0;
#pragma unroll
    for (int i = 0; i < 4; i++) {
        d[i] = (base + i < N_NODES) ? g_deg[base + i] : 0;
        s += d[i];
    }
    sc[tid] = s; __syncthreads();
    for (int off = 1; off < 256; off <<= 1) {
        int v = (tid >= off) ? sc[tid - off] : 0;
        __syncthreads();
        sc[tid] += v;
        __syncthreads();
    }
    int off = sOff + sc[tid] - s;
#pragma unroll
    for (int i = 0; i < 4; i++) {
        if (base + i < N_NODES) { g_rowptr[base + i] = off; g_cursor[base + i] = off; off += d[i]; }
    }
}

__global__ void k_fill(const int* __restrict__ ei) {
    int e2 = (blockIdx.x * blockDim.x + threadIdx.x) * 2;
    if (e2 + 1 < N_EDGES) {
        int2 s = *(const int2*)(ei + e2);
        int2 d = *(const int2*)(ei + N_EDGES + e2);
        int p0 = atomicAdd(&g_cursor[d.x], 1);
        g_col[p0] = s.x;
        int p1 = atomicAdd(&g_cursor[d.y], 1);
        g_col[p1] = s.y;
    } else if (e2 < N_EDGES) {
        int d = ei[N_EDGES + e2];
        int p = atomicAdd(&g_cursor[d], 1);
        g_col[p] = ei[e2];
    }
}

// ---------------- layer-0 aggregation (emb gather, 8-way unroll) ----------
__global__ void __launch_bounds__(256) k_aggr0(const int* __restrict__ x_idx,
                                               const float* __restrict__ emb,
                                               const float* __restrict__ epsArr,
                                               float* __restrict__ Hout) {
    int warp = (blockIdx.x * blockDim.x + threadIdx.x) >> 5;
    if (warp >= N_NODES) return;
    int lane = threadIdx.x & 31, c0 = lane * 2;
    float ev = 1.f + epsArr[0];
    int self = __ldg(&x_idx[warp]);
    float2 xv = *(const float2*)(emb + (size_t)self * HID + c0);
    float s0 = ev * xv.x, s1 = ev * xv.y;
    int start = g_rowptr[warp], deg = g_deg[warp];
    int j = 0;
    for (; j + 7 < deg; j += 8) {
        int n[8];
#pragma unroll
        for (int u = 0; u < 8; u++) n[u] = __ldg(&x_idx[g_col[start + j + u]]);
        float2 p[8];
#pragma unroll
        for (int u = 0; u < 8; u++) p[u] = *(const float2*)(emb + (size_t)n[u] * HID + c0);
#pragma unroll
        for (int u = 0; u < 8; u++) { s0 += p[u].x; s1 += p[u].y; }
    }
    for (; j + 1 < deg; j += 2) {
        int n0 = __ldg(&x_idx[g_col[start + j]]);
        int n1 = __ldg(&x_idx[g_col[start + j + 1]]);
        float2 p = *(const float2*)(emb + (size_t)n0 * HID + c0);
        float2 q = *(const float2*)(emb + (size_t)n1 * HID + c0);
        s0 += p.x + q.x; s1 += p.y + q.y;
    }
    if (j < deg) {
        int n0 = __ldg(&x_idx[g_col[start + j]]);
        float2 p = *(const float2*)(emb + (size_t)n0 * HID + c0);
        s0 += p.x; s1 += p.y;
    }
    *(float2*)(Hout + (size_t)warp * HID + c0) = make_float2(s0, s1);
}

// ---------------- aggregation l>=1 (BN affine gather, 8-way unroll) -------
__global__ void __launch_bounds__(256) k_aggr(const float* __restrict__ X,
                                              float* __restrict__ Hout,
                                              const float* __restrict__ epsArr,
                                              const float* __restrict__ statsIn,
                                              const float* __restrict__ gam,
                                              const float* __restrict__ bet,
                                              int layer) {
    __shared__ float sa[HID], sb[HID];
    int tid = threadIdx.x;
    if (tid < HID) {
        float s = statsIn[tid], q = statsIn[HID + tid];
        float m = s * INVN;
        float var = q * INVN - m * m;
        float a = gam[tid] * rsqrtf(var + 1e-5f);
        sa[tid] = a;
        sb[tid] = fmaf(-m, a, bet[tid]);
    }
    __syncthreads();
    int warp = (blockIdx.x * blockDim.x + tid) >> 5;
    if (warp >= N_NODES) return;
    int lane = tid & 31, c0 = lane * 2;
    float a0 = sa[c0], a1 = sa[c0 + 1], b0 = sb[c0], b1 = sb[c0 + 1];
    float ev = 1.f + epsArr[layer];

    float2 xv = *(const float2*)(X + (size_t)warp * HID + c0);
    float s0 = ev * fmaxf(fmaf(a0, xv.x, b0), 0.f);
    float s1 = ev * fmaxf(fmaf(a1, xv.y, b1), 0.f);

    int start = g_rowptr[warp], deg = g_deg[warp];
    int j = 0;
    for (; j + 7 < deg; j += 8) {
        int n[8];
#pragma unroll
        for (int u = 0; u < 8; u++) n[u] = g_col[start + j + u];
        float2 p[8];
#pragma unroll
        for (int u = 0; u < 8; u++) p[u] = *(const float2*)(X + (size_t)n[u] * HID + c0);
#pragma unroll
        for (int u = 0; u < 8; u++) {
            s0 += fmaxf(fmaf(a0, p[u].x, b0), 0.f);
            s1 += fmaxf(fmaf(a1, p[u].y, b1), 0.f);
        }
    }
    for (; j + 1 < deg; j += 2) {
        int n0 = g_col[start + j], n1 = g_col[start + j + 1];
        float2 p = *(const float2*)(X + (size_t)n0 * HID + c0);
        float2 q = *(const float2*)(X + (size_t)n1 * HID + c0);
        s0 += fmaxf(fmaf(a0, p.x, b0), 0.f) + fmaxf(fmaf(a0, q.x, b0), 0.f);
        s1 += fmaxf(fmaf(a1, p.y, b1), 0.f) + fmaxf(fmaf(a1, q.y, b1), 0.f);
    }
    if (j < deg) {
        int n0 = g_col[start + j];
        float2 p = *(const float2*)(X + (size_t)n0 * HID + c0);
        s0 += fmaxf(fmaf(a0, p.x, b0), 0.f);
        s1 += fmaxf(fmaf(a1, p.y, b1), 0.f);
    }
    *(float2*)(Hout + (size_t)warp * HID + c0) = make_float2(s0, s1);
}

// ---------------- GEMM1: Y1 = H @ W1[l] (R10-exact FFMA2) -----------------
#define G1_SMEM_FLOATS (128*64 + 64*128 + 2*128)
__global__ void __launch_bounds__(256, 2) k_gemm1(const float* __restrict__ A,
                                                  const float* __restrict__ W,
                                                  float* __restrict__ Y,
                                                  float* __restrict__ statsOut) {
    extern __shared__ float sm[];
    float* sA = sm;                 // [128][64]
    float* sW = sm + 128 * 64;      // [64][128] k-major
    float* sS = sW + 64 * 128;      // [256]
    int t = threadIdx.x;
    int row0 = blockIdx.x * 128;

    {   // W tile
        const float4* W4 = (const float4*)W;
        float4* sW4 = (float4*)sW;
#pragma unroll
        for (int i = 0; i < 8; i++) sW4[t + i * 256] = W4[t + i * 256];
    }
    {   // A tile
        int r = t >> 1, kh = (t & 1) * 32;
        int gr = row0 + r;
        float4* dst = (float4*)(sA + r * 64 + kh);
        if (gr < N_NODES) {
            const float4* src = (const float4*)(A + (size_t)gr * 64 + kh);
#pragma unroll
            for (int i = 0; i < 8; i++) dst[i] = src[i];
        } else {
#pragma unroll
            for (int i = 0; i < 8; i++) dst[i] = make_float4(0.f, 0.f, 0.f, 0.f);
        }
    }
    sS[t] = 0.f;
    __syncthreads();

    int tx = t & 15, ty = t >> 4;
    const float* aBase = sA + ty * 8 * 64;
    const float4* w4 = (const float4*)sW;

    u64t acc[8][4];
#pragma unroll
    for (int i = 0; i < 8; i++)
#pragma unroll
        for (int j = 0; j < 4; j++) acc[i][j] = pk2(0.f, 0.f);

#pragma unroll 8
    for (int k = 0; k < 64; k++) {
        float4 wa = w4[k * 32 + tx];
        float4 wb = w4[k * 32 + 16 + tx];
        u64t w01 = pk2(wa.x, wa.y), w23 = pk2(wa.z, wa.w);
        u64t w45 = pk2(wb.x, wb.y), w67 = pk2(wb.z, wb.w);
#pragma unroll
        for (int i = 0; i < 8; i++) {
            float a = aBase[i * 64 + k];
            u64t a2 = pk2(a, a);
            fma2(acc[i][0], a2, w01);
            fma2(acc[i][1], a2, w23);
            fma2(acc[i][2], a2, w45);
            fma2(acc[i][3], a2, w67);
        }
    }

    float cs[8], cq[8];
#pragma unroll
    for (int j = 0; j < 8; j++) { cs[j] = 0.f; cq[j] = 0.f; }
#pragma unroll
    for (int i = 0; i < 8; i++) {
        float2 p0 = up2(acc[i][0]), p1 = up2(acc[i][1]);
        float2 p2 = up2(acc[i][2]), p3 = up2(acc[i][3]);
        int gr = row0 + ty * 8 + i;
        if (gr < N_NODES) {
            *(float4*)(Y + (size_t)gr * 128 + tx * 4) = make_float4(p0.x, p0.y, p1.x, p1.y);
            *(float4*)(Y + (size_t)gr * 128 + 64 + tx * 4) = make_float4(p2.x, p2.y, p3.x, p3.y);
        }
        cs[0] += p0.x; cq[0] += p0.x * p0.x;
        cs[1] += p0.y; cq[1] += p0.y * p0.y;
        cs[2] += p1.x; cq[2] += p1.x * p1.x;
        cs[3] += p1.y; cq[3] += p1.y * p1.y;
        cs[4] += p2.x; cq[4] += p2.x * p2.x;
        cs[5] += p2.y; cq[5] += p2.y * p2.y;
        cs[6] += p3.x; cq[6] += p3.x * p3.x;
        cs[7] += p3.y; cq[7] += p3.y * p3.y;
    }
#pragma unroll
    for (int j = 0; j < 4; j++) {
        atomicAdd(&sS[tx * 4 + j], cs[j]);
        atomicAdd(&sS[128 + tx * 4 + j], cq[j]);
        atomicAdd(&sS[64 + tx * 4 + j], cs[4 + j]);
        atomicAdd(&sS[128 + 64 + tx * 4 + j], cq[4 + j]);
    }
    __syncthreads();
    atomicAdd(&statsOut[t], sS[t]);
}

// ---------------- GEMM2: row-pair FFMA2, transposed A tile (R10-exact) ----
#define SAT2 132
#define G2_SMEM_FLOATS (128*SAT2 + 128*64 + 128 + 2*128)
__global__ void __launch_bounds__(256, 2) k_gemm2(const float* __restrict__ Yin,
                                                  const float* __restrict__ W,
                                                  float* __restrict__ Xout,
                                                  const float* __restrict__ statsIn,
                                                  const float* __restrict__ gam,
                                                  const float* __restrict__ bet,
                                                  float* __restrict__ statsOut) {
    extern __shared__ float sm[];
    float* sAT = sm;                      // [128 k][SAT2]
    float* sW  = sm + 128 * SAT2;         // [128][64] k-major
    float* sS  = sW + 128 * 64;           // [128]
    float* sTa = sS + 128;
    float* sTb = sTa + 128;
    int t = threadIdx.x;
    int row0 = blockIdx.x * 128;

    if (t < 128) {
        float s = statsIn[t], q = statsIn[128 + t];
        float m = s * INVN;
        float var = q * INVN - m * m;
        float a = gam[t] * rsqrtf(var + 1e-5f);
        sTa[t] = a;
        sTb[t] = fmaf(-m, a, bet[t]);
        sS[t] = 0.f;
    }
    __syncthreads();

    {   // W tile
        const float4* W4 = (const float4*)W;
        float4* sW4 = (float4*)sW;
#pragma unroll
        for (int i = 0; i < 8; i++) sW4[t + i * 256] = W4[t + i * 256];
    }
    {   // A tile with BN+relu transform, stored TRANSPOSED [k][SAT2]
        int r = t >> 1, kh = (t & 1) * 64;
        int gr = row0 + r;
        if (gr < N_NODES) {
            const float4* src = (const float4*)(Yin + (size_t)gr * 128 + kh);
#pragma unroll
            for (int i = 0; i < 16; i++) {
                float4 y = src[i];
                float4 ta = *(const float4*)(sTa + kh + i * 4);
                float4 tb = *(const float4*)(sTb + kh + i * 4);
                int k0 = kh + i * 4;
                sAT[(k0 + 0) * SAT2 + r] = fmaxf(fmaf(ta.x, y.x, tb.x), 0.f);
                sAT[(k0 + 1) * SAT2 + r] = fmaxf(fmaf(ta.y, y.y, tb.y), 0.f);
                sAT[(k0 + 2) * SAT2 + r] = fmaxf(fmaf(ta.z, y.z, tb.z), 0.f);
                sAT[(k0 + 3) * SAT2 + r] = fmaxf(fmaf(ta.w, y.w, tb.w), 0.f);
            }
        } else {
#pragma unroll
            for (int i = 0; i < 16; i++) {
                int k0 = kh + i * 4;
                sAT[(k0 + 0) * SAT2 + r] = 0.f;
                sAT[(k0 + 1) * SAT2 + r] = 0.f;
                sAT[(k0 + 2) * SAT2 + r] = 0.f;
                sAT[(k0 + 3) * SAT2 + r] = 0.f;
            }
        }
    }
    __syncthreads();

    int tx = t & 15, ty = t >> 4;
    const float* aT = sAT + ty * 8;       // rows ty*8..ty*8+7
    const float4* w4 = (const float4*)sW;

    u64t acc[4][4];                       // [row-pair][col]
#pragma unroll
    for (int i = 0; i < 4; i++)
#pragma unroll
        for (int j = 0; j < 4; j++) acc[i][j] = pk2(0.f, 0.f);

#pragma unroll 8
    for (int k = 0; k < 128; k++) {
        float4 w = w4[k * 16 + tx];
        u64t w0 = pk2(w.x, w.x), w1 = pk2(w.y, w.y);
        u64t w2 = pk2(w.z, w.z), w3 = pk2(w.w, w.w);
        const u64t* ap = (const u64t*)(aT + k * SAT2);
        u64t a0 = ap[0], a1 = ap[1], a2 = ap[2], a3 = ap[3];
        fma2(acc[0][0], a0, w0); fma2(acc[0][1], a0, w1);
        fma2(acc[0][2], a0, w2); fma2(acc[0][3], a0, w3);
        fma2(acc[1][0], a1, w0); fma2(acc[1][1], a1, w1);
        fma2(acc[1][2], a1, w2); fma2(acc[1][3], a1, w3);
        fma2(acc[2][0], a2, w0); fma2(acc[2][1], a2, w1);
        fma2(acc[2][2], a2, w2); fma2(acc[2][3], a2, w3);
        fma2(acc[3][0], a3, w0); fma2(acc[3][1], a3, w1);
        fma2(acc[3][2], a3, w2); fma2(acc[3][3], a3, w3);
    }

    float cs[4] = {0.f, 0.f, 0.f, 0.f}, cq[4] = {0.f, 0.f, 0.f, 0.f};
#pragma unroll
    for (int rp = 0; rp < 4; rp++) {
        float2 p0 = up2(acc[rp][0]), p1 = up2(acc[rp][1]);
        float2 p2 = up2(acc[rp][2]), p3 = up2(acc[rp][3]);
        int gr = row0 + ty * 8 + rp * 2;
        if (gr < N_NODES)
            *(float4*)(Xout + (size_t)gr * 64 + tx * 4) = make_float4(p0.x, p1.x, p2.x, p3.x);
        if (gr + 1 < N_NODES)
            *(float4*)(Xout + (size_t)(gr + 1) * 64 + tx * 4) = make_float4(p0.y, p1.y, p2.y, p3.y);
        cs[0] += p0.x + p0.y; cq[0] += p0.x * p0.x + p0.y * p0.y;
        cs[1] += p1.x + p1.y; cq[1] += p1.x * p1.x + p1.y * p1.y;
        cs[2] += p2.x + p2.y; cq[2] += p2.x * p2.x + p2.y * p2.y;
        cs[3] += p3.x + p3.y; cq[3] += p3.x * p3.x + p3.y * p3.y;
    }
#pragma unroll
    for (int j = 0; j < 4; j++) {
        atomicAdd(&sS[tx * 4 + j], cs[j]);
        atomicAdd(&sS[64 + tx * 4 + j], cq[j]);
    }
    __syncthreads();
    if (t < 128) atomicAdd(&statsOut[t], sS[t]);
}

// ---------------- global mean pool per graph ------------------------------
__global__ void k_pool(const float* __restrict__ X, const int* __restrict__ batch,
                       const float* __restrict__ statsIn,
                       const float* __restrict__ gam, const float* __restrict__ bet) {
    __shared__ float sa[HID], sb[HID];
    __shared__ float sred[4][HID];
    __shared__ int s_lo, s_hi;
    int tid = threadIdx.x, g = blockIdx.x;
    if (tid < HID) {
        float s = statsIn[tid], q = statsIn[HID + tid];
        float m = s * INVN;
        float var = q * INVN - m * m;
        float a = gam[tid] * rsqrtf(var + 1e-5f);
        sa[tid] = a;
        sb[tid] = fmaf(-m, a, bet[tid]);
    }
    if (tid == 0) {
        int lo = 0, hi = N_NODES;
        while (lo < hi) { int mid = (lo + hi) >> 1; if (batch[mid] < g) lo = mid + 1; else hi = mid; }
        s_lo = lo;
        lo = 0; hi = N_NODES; int gg = g + 1;
        while (lo < hi) { int mid = (lo + hi) >> 1; if (batch[mid] < gg) lo = mid + 1; else hi = mid; }
        s_hi = lo;
    }
    __syncthreads();
    int c = tid & 63, rg = tid >> 6;
    float acc = 0.f;
    for (int r = s_lo + rg; r < s_hi; r += 4) {
        float v = fmaf(sa[c], X[(size_t)r * HID + c], sb[c]);
        acc += fmaxf(v, 0.f);
    }
    sred[rg][c] = acc; __syncthreads();
    if (tid < HID) {
        float s = sred[0][c] + sred[1][c] + sred[2][c] + sred[3][c];
        int cnt = s_hi - s_lo;
        g_reps[g * HID + c] = s / (float)(cnt > 0 ? cnt : 1);
    }
}

// ---------------- head GEMMs (in-kernel BN, R8-validated) -----------------
__global__ void kf_gemm(const float* __restrict__ A, const float* __restrict__ W,
                        float* __restrict__ out, float* __restrict__ statsOut,
                        const float* __restrict__ statsIn,
                        const float* __restrict__ gam, const float* __restrict__ bet,
                        int K, int N) {
    __shared__ float ta[DENSE], tb[DENSE];
    int r = blockIdx.x, n = threadIdx.x;
    if (statsIn != 0 && n < K) {
        float s = statsIn[n], q = statsIn[K + n];
        float m = s * INVG;
        float var = q * INVG - m * m;
        float a = gam[n] * rsqrtf(var + 1e-5f);
        ta[n] = a;
        tb[n] = fmaf(-m, a, bet[n]);
    }
    __syncthreads();
    float acc = 0.f;
    for (int k = 0; k < K; k++) {
        float av = A[r * K + k];
        if (statsIn != 0) av = fmaxf(fmaf(ta[k], av, tb[k]), 0.f);
        acc = fmaf(av, W[k * N + n], acc);
    }
    out[r * N + n] = acc;
    atomicAdd(&statsOut[n], acc);
    atomicAdd(&statsOut[N + n], acc * acc);
}

__global__ void kf_out(const float* __restrict__ T2v, const float* __restrict__ Wlin,
                       const float* __restrict__ blin, float* __restrict__ out,
                       const float* __restrict__ statsIn,
                       const float* __restrict__ gam, const float* __restrict__ bet) {
    __shared__ float ta[DENSE], tb[DENSE];
    int r = blockIdx.x, t = threadIdx.x;
    if (t < DENSE) {
        float s = statsIn[t], q = statsIn[DENSE + t];
        float m = s * INVG;
        float var = q * INVG - m * m;
        float a = gam[t] * rsqrtf(var + 1e-5f);
        ta[t] = a;
        tb[t] = fmaf(-m, a, bet[t]);
    }
    __syncthreads();
    if (t < OUTD) {
        float acc = blin[t];
        for (int k = 0; k < DENSE; k++) {
            float av = fmaxf(fmaf(ta[k], T2v[r * DENSE + k], tb[k]), 0.f);
            acc = fmaf(av, Wlin[k * OUTD + t], acc);
        }
        out[r * OUTD + t] = acc;
    }
}

// ---------------- launcher ------------------------------------------------
extern "C" void kernel_launch(void* const* d_in, const int* in_sizes, int n_in,
                              void* d_out, int out_size) {
    (void)in_sizes; (void)n_in; (void)out_size;
    const int*   x_idx = (const int*)d_in[0];
    const int*   ei    = (const int*)d_in[1];
    const int*   batch = (const int*)d_in[2];
    const float* emb   = (const float*)d_in[3];
    const float* eps   = (const float*)d_in[4];
    const float* W1    = (const float*)d_in[5];
    const float* g1    = (const float*)d_in[6];
    const float* b1    = (const float*)d_in[7];
    const float* W2    = (const float*)d_in[8];
    const float* g2    = (const float*)d_in[9];
    const float* b2    = (const float*)d_in[10];
    const float* Wf1   = (const float*)d_in[11];
    const float* gf1   = (const float*)d_in[12];
    const float* bf1   = (const float*)d_in[13];
    const float* Wf2   = (const float*)d_in[14];
    const float* gf2   = (const float*)d_in[15];
    const float* bf2   = (const float*)d_in[16];
    const float* Wlin  = (const float*)d_in[17];
    const float* blin  = (const float*)d_in[18];
    float* out = (float*)d_out;

    float *Xa, *H, *Y1, *s128, *s64, *sF, *reps, *T1, *T2;
    cudaGetSymbolAddress((void**)&Xa,   g_Xa);
    cudaGetSymbolAddress((void**)&H,    g_H);
    cudaGetSymbolAddress((void**)&Y1,   g_Y1);
    cudaGetSymbolAddress((void**)&s128, g_stats128);
    cudaGetSymbolAddress((void**)&s64,  g_stats64);
    cudaGetSymbolAddress((void**)&sF,   g_statsF);
    cudaGetSymbolAddress((void**)&reps, g_reps);
    cudaGetSymbolAddress((void**)&T1,   g_T1);
    cudaGetSymbolAddress((void**)&T2,   g_T2);

    static const size_t G1_BYTES = G1_SMEM_FLOATS * sizeof(float);
    static const size_t G2_BYTES = G2_SMEM_FLOATS * sizeof(float);
    cudaFuncSetAttribute(k_gemm1, cudaFuncAttributeMaxDynamicSharedMemorySize, (int)G1_BYTES);
    cudaFuncSetAttribute(k_gemm2, cudaFuncAttributeMaxDynamicSharedMemorySize, (int)G2_BYTES);

    k_setup<<<(N_NODES + 255) / 256, 256>>>();
    k_hist <<<(N_EDGES / 2 + 255) / 256, 256>>>(ei);
    k_scan1<<<SCAN_NB, 256>>>();
    k_scan3<<<SCAN_NB, 256>>>();
    k_fill <<<(N_EDGES / 2 + 255) / 256, 256>>>(ei);

    const int GEMM_GRID = (N_NODES + 127) / 128;   // 782
    for (int l = 0; l < 4; l++) {
        if (l == 0)
            k_aggr0<<<(N_NODES * 32 + 255) / 256, 256>>>(x_idx, emb, eps, H);
        else
            k_aggr<<<(N_NODES * 32 + 255) / 256, 256>>>(
                Xa, H, eps, s64 + (l - 1) * 2 * HID,
                g2 + (l - 1) * HID, b2 + (l - 1) * HID, l);
        k_gemm1<<<GEMM_GRID, 256, G1_BYTES>>>(H, W1 + (size_t)l * HID * DENSE, Y1,
                                              s128 + l * 2 * DENSE);
        k_gemm2<<<GEMM_GRID, 256, G2_BYTES>>>(Y1, W2 + (size_t)l * DENSE * HID, Xa,
                                              s128 + l * 2 * DENSE,
                                              g1 + l * DENSE, b1 + l * DENSE,
                                              s64 + l * 2 * HID);
    }
    k_pool<<<N_GRAPHS, 256>>>(Xa, batch, s64 + 3 * 2 * HID, g2 + 3 * HID, b2 + 3 * HID);

    kf_gemm<<<N_GRAPHS, DENSE>>>(reps, Wf1, T1, sF, (const float*)0,
                                 (const float*)0, (const float*)0, HID, DENSE);
    kf_gemm<<<N_GRAPHS, DENSE>>>(T1, Wf2, T2, sF + 2 * DENSE, sF, gf1, bf1, DENSE, DENSE);
    kf_out<<<N_GRAPHS, DENSE>>>(T2, Wlin, blin, out, sF + 2 * DENSE, gf2, bf2);
}

// round 13
// speedup vs baseline: 1.1544x; 1.0454x over previous
#include <cuda_runtime.h>

#define N_NODES 100000
#define N_EDGES 1600000
#define HID 64
#define DENSE 128
#define OUTD 10
#define N_GRAPHS 128
#define SCAN_NB 98
#define INVN (1.f / (float)N_NODES)
#define INVG (1.f / (float)N_GRAPHS)

typedef unsigned long long u64t;

// ---------------- packed f32x2 helpers (R3-proven) ------------------------
__device__ __forceinline__ u64t pk2(float lo, float hi) {
    u64t r; asm("mov.b64 %0,{%1,%2};" : "=l"(r) : "f"(lo), "f"(hi)); return r;
}
__device__ __forceinline__ void fma2(u64t& d, u64t a, u64t b) {
    asm("fma.rn.f32x2 %0,%1,%2,%0;" : "+l"(d) : "l"(a), "l"(b));
}
__device__ __forceinline__ float2 up2(u64t v) {
    float2 r; asm("mov.b64 {%0,%1},%2;" : "=f"(r.x), "=f"(r.y) : "l"(v)); return r;
}

// ---------------- device scratch ------------------------------------------
__device__ __align__(16) float g_Xa[N_NODES * HID];
__device__ __align__(16) float g_H [N_NODES * HID];
__device__ __align__(16) float g_Y1[N_NODES * DENSE];
__device__ int   g_deg[N_NODES];
__device__ int   g_rowptr[N_NODES];
__device__ int   g_cursor[N_NODES];
__device__ int   g_col[N_EDGES];
__device__ int   g_bsum[128];
__device__ __align__(16) float g_stats128[4 * 2 * DENSE];
__device__ __align__(16) float g_stats64 [4 * 2 * HID];
__device__ __align__(16) float g_statsF[4 * DENSE];
__device__ __align__(16) float g_T1[N_GRAPHS * DENSE];
__device__ __align__(16) float g_T2[N_GRAPHS * DENSE];

// ---------------- setup ---------------------------------------------------
__global__ void k_setup() {
    int t = blockIdx.x * blockDim.x + threadIdx.x;
    if (t < N_NODES)          g_deg[t] = 0;
    if (t < 4 * 2 * DENSE)    g_stats128[t] = 0.f;
    if (t < 4 * 2 * HID)      g_stats64[t]  = 0.f;
    if (t < 4 * DENSE)        g_statsF[t] = 0.f;
}

// ---------------- CSR build (4 edges per thread, int4) --------------------
__global__ void k_hist(const int* __restrict__ ei) {
    int e = (blockIdx.x * blockDim.x + threadIdx.x) * 4;
    if (e + 3 < N_EDGES) {
        int4 d = *(const int4*)(ei + N_EDGES + e);
        atomicAdd(&g_deg[d.x], 1);
        atomicAdd(&g_deg[d.y], 1);
        atomicAdd(&g_deg[d.z], 1);
        atomicAdd(&g_deg[d.w], 1);
    } else {
        for (int i = e; i < N_EDGES; i++) atomicAdd(&g_deg[ei[N_EDGES + i]], 1);
    }
}

__global__ void k_scan1() {
    __shared__ int ss[256];
    int tid = threadIdx.x;
    int base = blockIdx.x * 1024 + tid * 4;
    int s = 0;
#pragma unroll
    for (int i = 0; i < 4; i++) { int idx = base + i; if (idx < N_NODES) s += g_deg[idx]; }
    ss[tid] = s; __syncthreads();
    for (int off = 128; off > 0; off >>= 1) {
        if (tid < off) ss[tid] += ss[tid + off];
        __syncthreads();
    }
    if (tid == 0) g_bsum[blockIdx.x] = ss[0];   // raw block sums
}

// scan3 computes its own global offset (scan2 eliminated — R8-validated)
__global__ void k_scan3() {
    __shared__ int sc[256];
    __shared__ int sb2[128];
    __shared__ int sOff;
    int tid = threadIdx.x;
    if (tid < SCAN_NB) sb2[tid] = g_bsum[tid];
    __syncthreads();
    if (tid == 0) {
        int off = 0;
        for (int i = 0; i < (int)blockIdx.x; i++) off += sb2[i];
        sOff = off;
    }
    int base = blockIdx.x * 1024 + tid * 4;
    int d[4]; int s = 0;
#pragma unroll
    for (int i = 0; i < 4; i++) {
        d[i] = (base + i < N_NODES) ? g_deg[base + i] : 0;
        s += d[i];
    }
    sc[tid] = s; __syncthreads();
    for (int off = 1; off < 256; off <<= 1) {
        int v = (tid >= off) ? sc[tid - off] : 0;
        __syncthreads();
        sc[tid] += v;
        __syncthreads();
    }
    int off = sOff + sc[tid] - s;
#pragma unroll
    for (int i = 0; i < 4; i++) {
        if (base + i < N_NODES) { g_rowptr[base + i] = off; g_cursor[base + i] = off; off += d[i]; }
    }
}

__global__ void k_fill(const int* __restrict__ ei) {
    int e = (blockIdx.x * blockDim.x + threadIdx.x) * 4;
    if (e + 3 < N_EDGES) {
        int4 s = *(const int4*)(ei + e);
        int4 d = *(const int4*)(ei + N_EDGES + e);
        int p0 = atomicAdd(&g_cursor[d.x], 1); g_col[p0] = s.x;
        int p1 = atomicAdd(&g_cursor[d.y], 1); g_col[p1] = s.y;
        int p2 = atomicAdd(&g_cursor[d.z], 1); g_col[p2] = s.z;
        int p3 = atomicAdd(&g_cursor[d.w], 1); g_col[p3] = s.w;
    } else {
        for (int i = e; i < N_EDGES; i++) {
            int d = ei[N_EDGES + i];
            int p = atomicAdd(&g_cursor[d], 1);
            g_col[p] = ei[i];
        }
    }
}

// ---------------- layer-0 aggregation (emb gather, 8-way unroll) ----------
__global__ void __launch_bounds__(512) k_aggr0(const int* __restrict__ x_idx,
                                               const float* __restrict__ emb,
                                               const float* __restrict__ epsArr,
                                               float* __restrict__ Hout) {
    int warp = (blockIdx.x * blockDim.x + threadIdx.x) >> 5;
    if (warp >= N_NODES) return;
    int lane = threadIdx.x & 31, c0 = lane * 2;
    float ev = 1.f + epsArr[0];
    int self = __ldg(&x_idx[warp]);
    float2 xv = *(const float2*)(emb + (size_t)self * HID + c0);
    float s0 = ev * xv.x, s1 = ev * xv.y;
    int start = g_rowptr[warp], deg = g_deg[warp];
    int j = 0;
    for (; j + 7 < deg; j += 8) {
        int n[8];
#pragma unroll
        for (int u = 0; u < 8; u++) n[u] = __ldg(&x_idx[g_col[start + j + u]]);
        float2 p[8];
#pragma unroll
        for (int u = 0; u < 8; u++) p[u] = *(const float2*)(emb + (size_t)n[u] * HID + c0);
#pragma unroll
        for (int u = 0; u < 8; u++) { s0 += p[u].x; s1 += p[u].y; }
    }
    for (; j + 1 < deg; j += 2) {
        int n0 = __ldg(&x_idx[g_col[start + j]]);
        int n1 = __ldg(&x_idx[g_col[start + j + 1]]);
        float2 p = *(const float2*)(emb + (size_t)n0 * HID + c0);
        float2 q = *(const float2*)(emb + (size_t)n1 * HID + c0);
        s0 += p.x + q.x; s1 += p.y + q.y;
    }
    if (j < deg) {
        int n0 = __ldg(&x_idx[g_col[start + j]]);
        float2 p = *(const float2*)(emb + (size_t)n0 * HID + c0);
        s0 += p.x; s1 += p.y;
    }
    *(float2*)(Hout + (size_t)warp * HID + c0) = make_float2(s0, s1);
}

// ---------------- aggregation l>=1 (BN affine gather, 8-way unroll) -------
__global__ void __launch_bounds__(512) k_aggr(const float* __restrict__ X,
                                              float* __restrict__ Hout,
                                              const float* __restrict__ epsArr,
                                              const float* __restrict__ statsIn,
                                              const float* __restrict__ gam,
                                              const float* __restrict__ bet,
                                              int layer) {
    __shared__ float sa[HID], sb[HID];
    int tid = threadIdx.x;
    if (tid < HID) {
        float s = statsIn[tid], q = statsIn[HID + tid];
        float m = s * INVN;
        float var = q * INVN - m * m;
        float a = gam[tid] * rsqrtf(var + 1e-5f);
        sa[tid] = a;
        sb[tid] = fmaf(-m, a, bet[tid]);
    }
    __syncthreads();
    int warp = (blockIdx.x * blockDim.x + tid) >> 5;
    if (warp >= N_NODES) return;
    int lane = tid & 31, c0 = lane * 2;
    float a0 = sa[c0], a1 = sa[c0 + 1], b0 = sb[c0], b1 = sb[c0 + 1];
    float ev = 1.f + epsArr[layer];

    float2 xv = *(const float2*)(X + (size_t)warp * HID + c0);
    float s0 = ev * fmaxf(fmaf(a0, xv.x, b0), 0.f);
    float s1 = ev * fmaxf(fmaf(a1, xv.y, b1), 0.f);

    int start = g_rowptr[warp], deg = g_deg[warp];
    int j = 0;
    for (; j + 7 < deg; j += 8) {
        int n[8];
#pragma unroll
        for (int u = 0; u < 8; u++) n[u] = g_col[start + j + u];
        float2 p[8];
#pragma unroll
        for (int u = 0; u < 8; u++) p[u] = *(const float2*)(X + (size_t)n[u] * HID + c0);
#pragma unroll
        for (int u = 0; u < 8; u++) {
            s0 += fmaxf(fmaf(a0, p[u].x, b0), 0.f);
            s1 += fmaxf(fmaf(a1, p[u].y, b1), 0.f);
        }
    }
    for (; j + 1 < deg; j += 2) {
        int n0 = g_col[start + j], n1 = g_col[start + j + 1];
        float2 p = *(const float2*)(X + (size_t)n0 * HID + c0);
        float2 q = *(const float2*)(X + (size_t)n1 * HID + c0);
        s0 += fmaxf(fmaf(a0, p.x, b0), 0.f) + fmaxf(fmaf(a0, q.x, b0), 0.f);
        s1 += fmaxf(fmaf(a1, p.y, b1), 0.f) + fmaxf(fmaf(a1, q.y, b1), 0.f);
    }
    if (j < deg) {
        int n0 = g_col[start + j];
        float2 p = *(const float2*)(X + (size_t)n0 * HID + c0);
        s0 += fmaxf(fmaf(a0, p.x, b0), 0.f);
        s1 += fmaxf(fmaf(a1, p.y, b1), 0.f);
    }
    *(float2*)(Hout + (size_t)warp * HID + c0) = make_float2(s0, s1);
}

// ---------------- GEMM1: Y1 = H @ W1[l] (R10-exact FFMA2) -----------------
#define G1_SMEM_FLOATS (128*64 + 64*128 + 2*128)
__global__ void __launch_bounds__(256, 2) k_gemm1(const float* __restrict__ A,
                                                  const float* __restrict__ W,
                                                  float* __restrict__ Y,
                                                  float* __restrict__ statsOut) {
    extern __shared__ float sm[];
    float* sA = sm;                 // [128][64]
    float* sW = sm + 128 * 64;      // [64][128] k-major
    float* sS = sW + 64 * 128;      // [256]
    int t = threadIdx.x;
    int row0 = blockIdx.x * 128;

    {   // W tile
        const float4* W4 = (const float4*)W;
        float4* sW4 = (float4*)sW;
#pragma unroll
        for (int i = 0; i < 8; i++) sW4[t + i * 256] = W4[t + i * 256];
    }
    {   // A tile
        int r = t >> 1, kh = (t & 1) * 32;
        int gr = row0 + r;
        float4* dst = (float4*)(sA + r * 64 + kh);
        if (gr < N_NODES) {
            const float4* src = (const float4*)(A + (size_t)gr * 64 + kh);
#pragma unroll
            for (int i = 0; i < 8; i++) dst[i] = src[i];
        } else {
#pragma unroll
            for (int i = 0; i < 8; i++) dst[i] = make_float4(0.f, 0.f, 0.f, 0.f);
        }
    }
    sS[t] = 0.f;
    __syncthreads();

    int tx = t & 15, ty = t >> 4;
    const float* aBase = sA + ty * 8 * 64;
    const float4* w4 = (const float4*)sW;

    u64t acc[8][4];
#pragma unroll
    for (int i = 0; i < 8; i++)
#pragma unroll
        for (int j = 0; j < 4; j++) acc[i][j] = pk2(0.f, 0.f);

#pragma unroll 8
    for (int k = 0; k < 64; k++) {
        float4 wa = w4[k * 32 + tx];
        float4 wb = w4[k * 32 + 16 + tx];
        u64t w01 = pk2(wa.x, wa.y), w23 = pk2(wa.z, wa.w);
        u64t w45 = pk2(wb.x, wb.y), w67 = pk2(wb.z, wb.w);
#pragma unroll
        for (int i = 0; i < 8; i++) {
            float a = aBase[i * 64 + k];
            u64t a2 = pk2(a, a);
            fma2(acc[i][0], a2, w01);
            fma2(acc[i][1], a2, w23);
            fma2(acc[i][2], a2, w45);
            fma2(acc[i][3], a2, w67);
        }
    }

    float cs[8], cq[8];
#pragma unroll
    for (int j = 0; j < 8; j++) { cs[j] = 0.f; cq[j] = 0.f; }
#pragma unroll
    for (int i = 0; i < 8; i++) {
        float2 p0 = up2(acc[i][0]), p1 = up2(acc[i][1]);
        float2 p2 = up2(acc[i][2]), p3 = up2(acc[i][3]);
        int gr = row0 + ty * 8 + i;
        if (gr < N_NODES) {
            *(float4*)(Y + (size_t)gr * 128 + tx * 4) = make_float4(p0.x, p0.y, p1.x, p1.y);
            *(float4*)(Y + (size_t)gr * 128 + 64 + tx * 4) = make_float4(p2.x, p2.y, p3.x, p3.y);
        }
        cs[0] += p0.x; cq[0] += p0.x * p0.x;
        cs[1] += p0.y; cq[1] += p0.y * p0.y;
        cs[2] += p1.x; cq[2] += p1.x * p1.x;
        cs[3] += p1.y; cq[3] += p1.y * p1.y;
        cs[4] += p2.x; cq[4] += p2.x * p2.x;
        cs[5] += p2.y; cq[5] += p2.y * p2.y;
        cs[6] += p3.x; cq[6] += p3.x * p3.x;
        cs[7] += p3.y; cq[7] += p3.y * p3.y;
    }
#pragma unroll
    for (int j = 0; j < 4; j++) {
        atomicAdd(&sS[tx * 4 + j], cs[j]);
        atomicAdd(&sS[128 + tx * 4 + j], cq[j]);
        atomicAdd(&sS[64 + tx * 4 + j], cs[4 + j]);
        atomicAdd(&sS[128 + 64 + tx * 4 + j], cq[4 + j]);
    }
    __syncthreads();
    atomicAdd(&statsOut[t], sS[t]);
}

// ---------------- GEMM2: row-pair FFMA2, transposed A tile (R10-exact) ----
#define SAT2 132
#define G2_SMEM_FLOATS (128*SAT2 + 128*64 + 128 + 2*128)
__global__ void __launch_bounds__(256, 2) k_gemm2(const float* __restrict__ Yin,
                                                  const float* __restrict__ W,
                                                  float* __restrict__ Xout,
                                                  const float* __restrict__ statsIn,
                                                  const float* __restrict__ gam,
                                                  const float* __restrict__ bet,
                                                  float* __restrict__ statsOut) {
    extern __shared__ float sm[];
    float* sAT = sm;                      // [128 k][SAT2]
    float* sW  = sm + 128 * SAT2;         // [128][64] k-major
    float* sS  = sW + 128 * 64;           // [128]
    float* sTa = sS + 128;
    float* sTb = sTa + 128;
    int t = threadIdx.x;
    int row0 = blockIdx.x * 128;

    if (t < 128) {
        float s = statsIn[t], q = statsIn[128 + t];
        float m = s * INVN;
        float var = q * INVN - m * m;
        float a = gam[t] * rsqrtf(var + 1e-5f);
        sTa[t] = a;
        sTb[t] = fmaf(-m, a, bet[t]);
        sS[t] = 0.f;
    }
    __syncthreads();

    {   // W tile
        const float4* W4 = (const float4*)W;
        float4* sW4 = (float4*)sW;
#pragma unroll
        for (int i = 0; i < 8; i++) sW4[t + i * 256] = W4[t + i * 256];
    }
    {   // A tile with BN+relu transform, stored TRANSPOSED [k][SAT2]
        int r = t >> 1, kh = (t & 1) * 64;
        int gr = row0 + r;
        if (gr < N_NODES) {
            const float4* src = (const float4*)(Yin + (size_t)gr * 128 + kh);
#pragma unroll
            for (int i = 0; i < 16; i++) {
                float4 y = src[i];
                float4 ta = *(const float4*)(sTa + kh + i * 4);
                float4 tb = *(const float4*)(sTb + kh + i * 4);
                int k0 = kh + i * 4;
                sAT[(k0 + 0) * SAT2 + r] = fmaxf(fmaf(ta.x, y.x, tb.x), 0.f);
                sAT[(k0 + 1) * SAT2 + r] = fmaxf(fmaf(ta.y, y.y, tb.y), 0.f);
                sAT[(k0 + 2) * SAT2 + r] = fmaxf(fmaf(ta.z, y.z, tb.z), 0.f);
                sAT[(k0 + 3) * SAT2 + r] = fmaxf(fmaf(ta.w, y.w, tb.w), 0.f);
            }
        } else {
#pragma unroll
            for (int i = 0; i < 16; i++) {
                int k0 = kh + i * 4;
                sAT[(k0 + 0) * SAT2 + r] = 0.f;
                sAT[(k0 + 1) * SAT2 + r] = 0.f;
                sAT[(k0 + 2) * SAT2 + r] = 0.f;
                sAT[(k0 + 3) * SAT2 + r] = 0.f;
            }
        }
    }
    __syncthreads();

    int tx = t & 15, ty = t >> 4;
    const float* aT = sAT + ty * 8;       // rows ty*8..ty*8+7
    const float4* w4 = (const float4*)sW;

    u64t acc[4][4];                       // [row-pair][col]
#pragma unroll
    for (int i = 0; i < 4; i++)
#pragma unroll
        for (int j = 0; j < 4; j++) acc[i][j] = pk2(0.f, 0.f);

#pragma unroll 8
    for (int k = 0; k < 128; k++) {
        float4 w = w4[k * 16 + tx];
        u64t w0 = pk2(w.x, w.x), w1 = pk2(w.y, w.y);
        u64t w2 = pk2(w.z, w.z), w3 = pk2(w.w, w.w);
        const u64t* ap = (const u64t*)(aT + k * SAT2);
        u64t a0 = ap[0], a1 = ap[1], a2 = ap[2], a3 = ap[3];
        fma2(acc[0][0], a0, w0); fma2(acc[0][1], a0, w1);
        fma2(acc[0][2], a0, w2); fma2(acc[0][3], a0, w3);
        fma2(acc[1][0], a1, w0); fma2(acc[1][1], a1, w1);
        fma2(acc[1][2], a1, w2); fma2(acc[1][3], a1, w3);
        fma2(acc[2][0], a2, w0); fma2(acc[2][1], a2, w1);
        fma2(acc[2][2], a2, w2); fma2(acc[2][3], a2, w3);
        fma2(acc[3][0], a3, w0); fma2(acc[3][1], a3, w1);
        fma2(acc[3][2], a3, w2); fma2(acc[3][3], a3, w3);
    }

    float cs[4] = {0.f, 0.f, 0.f, 0.f}, cq[4] = {0.f, 0.f, 0.f, 0.f};
#pragma unroll
    for (int rp = 0; rp < 4; rp++) {
        float2 p0 = up2(acc[rp][0]), p1 = up2(acc[rp][1]);
        float2 p2 = up2(acc[rp][2]), p3 = up2(acc[rp][3]);
        int gr = row0 + ty * 8 + rp * 2;
        if (gr < N_NODES)
            *(float4*)(Xout + (size_t)gr * 64 + tx * 4) = make_float4(p0.x, p1.x, p2.x, p3.x);
        if (gr + 1 < N_NODES)
            *(float4*)(Xout + (size_t)(gr + 1) * 64 + tx * 4) = make_float4(p0.y, p1.y, p2.y, p3.y);
        cs[0] += p0.x + p0.y; cq[0] += p0.x * p0.x + p0.y * p0.y;
        cs[1] += p1.x + p1.y; cq[1] += p1.x * p1.x + p1.y * p1.y;
        cs[2] += p2.x + p2.y; cq[2] += p2.x * p2.x + p2.y * p2.y;
        cs[3] += p3.x + p3.y; cq[3] += p3.x * p3.x + p3.y * p3.y;
    }
#pragma unroll
    for (int j = 0; j < 4; j++) {
        atomicAdd(&sS[tx * 4 + j], cs[j]);
        atomicAdd(&sS[64 + tx * 4 + j], cq[j]);
    }
    __syncthreads();
    if (t < 128) atomicAdd(&statsOut[t], sS[t]);
}

// ---------------- pool + head GEMM #1 fused (block == graph) --------------
__global__ void k_pool(const float* __restrict__ X, const int* __restrict__ batch,
                       const float* __restrict__ statsIn,
                       const float* __restrict__ gam, const float* __restrict__ bet,
                       const float* __restrict__ Wf1, float* __restrict__ T1,
                       float* __restrict__ statsOut) {
    __shared__ float sa[HID], sb[HID];
    __shared__ float sred[4][HID];
    __shared__ float srep[HID];
    __shared__ int s_lo, s_hi;
    int tid = threadIdx.x, g = blockIdx.x;
    if (tid < HID) {
        float s = statsIn[tid], q = statsIn[HID + tid];
        float m = s * INVN;
        float var = q * INVN - m * m;
        float a = gam[tid] * rsqrtf(var + 1e-5f);
        sa[tid] = a;
        sb[tid] = fmaf(-m, a, bet[tid]);
    }
    if (tid == 0) {
        int lo = 0, hi = N_NODES;
        while (lo < hi) { int mid = (lo + hi) >> 1; if (batch[mid] < g) lo = mid + 1; else hi = mid; }
        s_lo = lo;
        lo = 0; hi = N_NODES; int gg = g + 1;
        while (lo < hi) { int mid = (lo + hi) >> 1; if (batch[mid] < gg) lo = mid + 1; else hi = mid; }
        s_hi = lo;
    }
    __syncthreads();
    int c = tid & 63, rg = tid >> 6;
    float acc = 0.f;
    for (int r = s_lo + rg; r < s_hi; r += 4) {
        float v = fmaf(sa[c], X[(size_t)r * HID + c], sb[c]);
        acc += fmaxf(v, 0.f);
    }
    sred[rg][c] = acc; __syncthreads();
    if (tid < HID) {
        float s = sred[0][c] + sred[1][c] + sred[2][c] + sred[3][c];
        int cnt = s_hi - s_lo;
        srep[c] = s / (float)(cnt > 0 ? cnt : 1);
    }
    __syncthreads();
    // head GEMM #1: T1[g] = reps[g] @ Wf1 (64 -> 128) + stats
    if (tid < DENSE) {
        float a2 = 0.f;
        for (int k = 0; k < HID; k++)
            a2 = fmaf(srep[k], Wf1[k * DENSE + tid], a2);
        T1[g * DENSE + tid] = a2;
        atomicAdd(&statsOut[tid], a2);
        atomicAdd(&statsOut[DENSE + tid], a2 * a2);
    }
}

// ---------------- head GEMM #2 + output (in-kernel BN) --------------------
__global__ void kf_gemm(const float* __restrict__ A, const float* __restrict__ W,
                        float* __restrict__ out, float* __restrict__ statsOut,
                        const float* __restrict__ statsIn,
                        const float* __restrict__ gam, const float* __restrict__ bet,
                        int K, int N) {
    __shared__ float ta[DENSE], tb[DENSE];
    int r = blockIdx.x, n = threadIdx.x;
    if (n < K) {
        float s = statsIn[n], q = statsIn[K + n];
        float m = s * INVG;
        float var = q * INVG - m * m;
        float a = gam[n] * rsqrtf(var + 1e-5f);
        ta[n] = a;
        tb[n] = fmaf(-m, a, bet[n]);
    }
    __syncthreads();
    float acc = 0.f;
    for (int k = 0; k < K; k++) {
        float av = fmaxf(fmaf(ta[k], A[r * K + k], tb[k]), 0.f);
        acc = fmaf(av, W[k * N + n], acc);
    }
    out[r * N + n] = acc;
    atomicAdd(&statsOut[n], acc);
    atomicAdd(&statsOut[N + n], acc * acc);
}

__global__ void kf_out(const float* __restrict__ T2v, const float* __restrict__ Wlin,
                       const float* __restrict__ blin, float* __restrict__ out,
                       const float* __restrict__ statsIn,
                       const float* __restrict__ gam, const float* __restrict__ bet) {
    __shared__ float ta[DENSE], tb[DENSE];
    int r = blockIdx.x, t = threadIdx.x;
    if (t < DENSE) {
        float s = statsIn[t], q = statsIn[DENSE + t];
        float m = s * INVG;
        float var = q * INVG - m * m;
        float a = gam[t] * rsqrtf(var + 1e-5f);
        ta[t] = a;
        tb[t] = fmaf(-m, a, bet[t]);
    }
    __syncthreads();
    if (t < OUTD) {
        float acc = blin[t];
        for (int k = 0; k < DENSE; k++) {
            float av = fmaxf(fmaf(ta[k], T2v[r * DENSE + k], tb[k]), 0.f);
            acc = fmaf(av, Wlin[k * OUTD + t], acc);
        }
        out[r * OUTD + t] = acc;
    }
}

// ---------------- launcher ------------------------------------------------
extern "C" void kernel_launch(void* const* d_in, const int* in_sizes, int n_in,
                              void* d_out, int out_size) {
    (void)in_sizes; (void)n_in; (void)out_size;
    const int*   x_idx = (const int*)d_in[0];
    const int*   ei    = (const int*)d_in[1];
    const int*   batch = (const int*)d_in[2];
    const float* emb   = (const float*)d_in[3];
    const float* eps   = (const float*)d_in[4];
    const float* W1    = (const float*)d_in[5];
    const float* g1    = (const float*)d_in[6];
    const float* b1    = (const float*)d_in[7];
    const float* W2    = (const float*)d_in[8];
    const float* g2    = (const float*)d_in[9];
    const float* b2    = (const float*)d_in[10];
    const float* Wf1   = (const float*)d_in[11];
    const float* gf1   = (const float*)d_in[12];
    const float* bf1   = (const float*)d_in[13];
    const float* Wf2   = (const float*)d_in[14];
    const float* gf2   = (const float*)d_in[15];
    const float* bf2   = (const float*)d_in[16];
    const float* Wlin  = (const float*)d_in[17];
    const float* blin  = (const float*)d_in[18];
    float* out = (float*)d_out;

    float *Xa, *H, *Y1, *s128, *s64, *sF, *T1, *T2;
    cudaGetSymbolAddress((void**)&Xa,   g_Xa);
    cudaGetSymbolAddress((void**)&H,    g_H);
    cudaGetSymbolAddress((void**)&Y1,   g_Y1);
    cudaGetSymbolAddress((void**)&s128, g_stats128);
    cudaGetSymbolAddress((void**)&s64,  g_stats64);
    cudaGetSymbolAddress((void**)&sF,   g_statsF);
    cudaGetSymbolAddress((void**)&T1,   g_T1);
    cudaGetSymbolAddress((void**)&T2,   g_T2);

    static const size_t G1_BYTES = G1_SMEM_FLOATS * sizeof(float);
    static const size_t G2_BYTES = G2_SMEM_FLOATS * sizeof(float);
    cudaFuncSetAttribute(k_gemm1, cudaFuncAttributeMaxDynamicSharedMemorySize, (int)G1_BYTES);
    cudaFuncSetAttribute(k_gemm2, cudaFuncAttributeMaxDynamicSharedMemorySize, (int)G2_BYTES);

    k_setup<<<(N_NODES + 255) / 256, 256>>>();
    k_hist <<<(N_EDGES / 4 + 255) / 256, 256>>>(ei);
    k_scan1<<<SCAN_NB, 256>>>();
    k_scan3<<<SCAN_NB, 256>>>();
    k_fill <<<(N_EDGES / 4 + 255) / 256, 256>>>(ei);

    const int GEMM_GRID = (N_NODES + 127) / 128;   // 782
    for (int l = 0; l < 4; l++) {
        if (l == 0)
            k_aggr0<<<(N_NODES * 32 + 511) / 512, 512>>>(x_idx, emb, eps, H);
        else
            k_aggr<<<(N_NODES * 32 + 511) / 512, 512>>>(
                Xa, H, eps, s64 + (l - 1) * 2 * HID,
                g2 + (l - 1) * HID, b2 + (l - 1) * HID, l);
        k_gemm1<<<GEMM_GRID, 256, G1_BYTES>>>(H, W1 + (size_t)l * HID * DENSE, Y1,
                                              s128 + l * 2 * DENSE);
        k_gemm2<<<GEMM_GRID, 256, G2_BYTES>>>(Y1, W2 + (size_t)l * DENSE * HID, Xa,
                                              s128 + l * 2 * DENSE,
                                              g1 + l * DENSE, b1 + l * DENSE,
                                              s64 + l * 2 * HID);
    }
    k_pool<<<N_GRAPHS, 256>>>(Xa, batch, s64 + 3 * 2 * HID, g2 + 3 * HID, b2 + 3 * HID,
                              Wf1, T1, sF);

    kf_gemm<<<N_GRAPHS, DENSE>>>(T1, Wf2, T2, sF + 2 * DENSE, sF, gf1, bf1, DENSE, DENSE);
    kf_out<<<N_GRAPHS, DENSE>>>(T2, Wlin, blin, out, sF + 2 * DENSE, gf2, bf2);
}